// round 1
// baseline (speedup 1.0000x reference)
#include <cuda_runtime.h>

#define NB   32
#define NA   8400
#define ROWF 85
#define MD   300
#define TOTAL (NB*NA)
#define CONF_T 0.2f
#define NMS_T  0.45f

// output layout: concatenated float32, reference return order
#define OF_BOX  0         // 32*300*4 = 38400
#define OF_INZ  38400     // 9600
#define OF_SC   48000     // 9600
#define OF_CLS  57600     // 9600
#define OF_CTR  67200     // 19200
#define OF_KEEP 86400     // 9600  -> total 96000

__device__ unsigned long long g_keys[TOTAL];   // (ordered score)<<32 | ~anchor_idx
__device__ float4 g_aux[TOTAL*2];              // [x1,y1,x2,y2] , [obj,conf,cls,0]

// ---------------------------------------------------------------------------
// Kernel A: per-anchor score/decode. Memory bound (91.4 MB read).
// 128 anchors per block staged through smem with float4 coalesced loads.
// ---------------------------------------------------------------------------
__global__ void __launch_bounds__(128) score_kernel(const float* __restrict__ pred)
{
    __shared__ float sm[128 * ROWF];
    const float4* src = reinterpret_cast<const float4*>(pred) +
                        (size_t)blockIdx.x * (128 * ROWF / 4);
    float4* dst = reinterpret_cast<float4*>(sm);
#pragma unroll
    for (int i = threadIdx.x; i < 128 * ROWF / 4; i += 128) dst[i] = src[i];
    __syncthreads();

    const int t = threadIdx.x;
    const float* a = sm + t * ROWF;                 // stride 85: conflict-free

    float x = a[0], y = a[1], w = a[2], h = a[3], obj = a[4];

    // max over 80 classes, 4 independent chains for ILP (order-invariant, exact)
    float m0 = a[5], m1 = a[6], m2 = a[7], m3 = a[8];
#pragma unroll
    for (int k = 9; k < 85; k += 4) {
        m0 = fmaxf(m0, a[k]);   m1 = fmaxf(m1, a[k+1]);
        m2 = fmaxf(m2, a[k+2]); m3 = fmaxf(m3, a[k+3]);
    }
    float conf = fmaxf(fmaxf(m0, m1), fmaxf(m2, m3));

    // argmax = first index equal to the max (descending scan, last write wins)
    int cls = 0;
#pragma unroll
    for (int k = 79; k >= 0; --k) { if (a[5+k] == conf) cls = k; }

    float score = __fmul_rn(obj, conf);             // bit-exact vs reference

    int g    = blockIdx.x * 128 + t;
    int aidx = g % NA;

    unsigned long long key = 0ull;                  // below-threshold / -inf => 0
    if (score >= CONF_T) {
        unsigned ub = __float_as_uint(score) | 0x80000000u;  // score>0: ordered bits
        key = ((unsigned long long)ub << 32) | (unsigned)(~(unsigned)aidx);
    }
    g_keys[g] = key;

    float hw = __fmul_rn(w, 0.5f), hh = __fmul_rn(h, 0.5f);   // exact *0.5
    g_aux[2*g]   = make_float4(__fadd_rn(x,-hw), __fadd_rn(y,-hh),
                               __fadd_rn(x, hw), __fadd_rn(y, hh));
    g_aux[2*g+1] = make_float4(obj, conf, (float)cls, 0.f);
}

// ---------------------------------------------------------------------------
// Kernel B: per-batch block. radix-select -> bitonic sort 512 -> gather ->
// IoU bitmask -> sequential NMS scan -> zone test -> outputs.
// ---------------------------------------------------------------------------
__global__ void __launch_bounds__(512) nms_kernel(const float* __restrict__ zone,
                                                  float* __restrict__ out)
{
    __shared__ unsigned hist[256];
    __shared__ unsigned sh_prefix, sh_acc, ncand;
    __shared__ unsigned long long cand[512];
    __shared__ float4 bbox[MD];
    __shared__ float  bA[MD];
    __shared__ int    inside[MD];
    __shared__ unsigned maskw[MD * 10];
    __shared__ unsigned keepw[10];
    __shared__ unsigned validw[10];

    const int b   = blockIdx.x;
    const int tid = threadIdx.x;
    const unsigned long long* keys = g_keys + (size_t)b * NA;

    if (tid == 0) { sh_prefix = 0u; sh_acc = 0u; ncand = 0u; }
    if (tid < 10) validw[tid] = 0u;

    // ---- 3-pass radix select on top 24 bits of the ordered score ----
    unsigned prefix = 0u;
    for (int pass = 0; pass < 3; ++pass) {
        if (tid < 256) hist[tid] = 0u;
        __syncthreads();
        for (int i = tid; i < NA; i += 512) {
            unsigned h24 = (unsigned)(keys[i] >> 40);
            unsigned hi  = h24 >> (8 * (3 - pass));      // pass0: >>24 == 0
            if (hi == prefix) {
                unsigned bin = (h24 >> (8 * (2 - pass))) & 255u;
                atomicAdd(&hist[bin], 1u);
            }
        }
        __syncthreads();
        if (tid == 0) {
            unsigned acc = sh_acc, cum = 0u; int sel = 0;
            for (int bin = 255; bin >= 0; --bin) {
                unsigned c = hist[bin];
                if (acc + cum + c >= (unsigned)MD) { sel = bin; break; }
                cum += c;
            }
            sh_acc    = acc + cum;
            sh_prefix = (sh_prefix << 8) | (unsigned)sel;
        }
        __syncthreads();
        prefix = sh_prefix;
    }

    // ---- collect all candidates with 24-bit prefix >= threshold ----
    for (int i = tid; i < NA; i += 512) {
        unsigned long long k = keys[i];
        if ((unsigned)(k >> 40) >= prefix) {
            unsigned p = atomicAdd(&ncand, 1u);
            if (p < 512u) cand[p] = k;
        }
    }
    __syncthreads();
    unsigned nc = ncand; if (nc > 512u) nc = 512u;
    if ((unsigned)tid >= nc) cand[tid] = 0ull;
    __syncthreads();

    // ---- bitonic sort 512, descending (exact top_k order incl. tie-break) ----
    for (int size = 2; size <= 512; size <<= 1) {
        for (int stride = size >> 1; stride > 0; stride >>= 1) {
            int partner = tid ^ stride;
            if (partner > tid) {
                unsigned long long u = cand[tid], v = cand[partner];
                bool desc = ((tid & size) == 0);
                if (desc ? (u < v) : (u > v)) { cand[tid] = v; cand[partner] = u; }
            }
            __syncthreads();
        }
    }

    // ---- gather top 300, emit order-independent outputs, zone test ----
    if (tid < MD) {
        unsigned long long kk = cand[tid];
        unsigned aidx = ~((unsigned)kk);
        bool valid = (kk >> 32) != 0ull;
        if (!valid) aidx = 0;                       // safety (never expected)
        size_t g = (size_t)b * NA + aidx;
        float4 v0 = g_aux[2*g], v1 = g_aux[2*g+1];
        bbox[tid] = v0;
        bA[tid] = __fmul_rn(fmaxf(__fadd_rn(v0.z, -v0.x), 0.f),
                            fmaxf(__fadd_rn(v0.w, -v0.y), 0.f));
        if (valid) atomicOr(&validw[tid >> 5], 1u << (tid & 31));

        float cx = __fmul_rn(__fadd_rn(v0.x, v0.z), 0.5f);
        float cy = __fmul_rn(__fadd_rn(v0.y, v0.w), 0.5f);

        int cnt = 0;
#pragma unroll
        for (int k2 = 0; k2 < 8; ++k2) {
            int km = (k2 + 7) & 7;
            float xi = zone[2*k2], yi = zone[2*k2+1];
            float xj = zone[2*km], yj = zone[2*km+1];
            bool gyi = yi > cy, gyj = yj > cy;
            if (gyi != gyj) {
                float gx = __fadd_rn(
                    __fdiv_rn(__fmul_rn(__fadd_rn(xj,-xi), __fadd_rn(cy,-yi)),
                              __fadd_rn(yj,-yi)), xi);
                if (gx > cx) cnt++;
            }
        }
        inside[tid] = cnt & 1;

        size_t o = (size_t)b * MD + tid;
        out[OF_BOX + o*4 + 0] = v0.y;  out[OF_BOX + o*4 + 1] = v0.x;
        out[OF_BOX + o*4 + 2] = v0.w;  out[OF_BOX + o*4 + 3] = v0.z;
        out[OF_SC  + o]       = fmaxf(v1.x, v1.y);
        out[OF_CLS + o]       = v1.z;
        out[OF_CTR + o*2]     = cy;    out[OF_CTR + o*2 + 1] = cx;
    }
    __syncthreads();

    // ---- suppression bitmask: warp w owns columns [w*32, w*32+32) ----
    {
        int w = tid >> 5, l = tid & 31;
        if (w < 10) {
            int j = tid;
            bool jv = (j < MD);
            float4 bj = jv ? bbox[j] : make_float4(0,0,0,0);
            float  ja = jv ? bA[j] : 0.f;
            for (int i = 0; i < MD; ++i) {
                float4 bi = bbox[i];            // broadcast LDS
                float  ia = bA[i];
                bool sup = false;
                if (jv && j > i) {
                    float ltx = fmaxf(bi.x, bj.x), lty = fmaxf(bi.y, bj.y);
                    float rbx = fminf(bi.z, bj.z), rby = fminf(bi.w, bj.w);
                    float iw  = fmaxf(__fadd_rn(rbx, -ltx), 0.f);
                    float ih  = fmaxf(__fadd_rn(rby, -lty), 0.f);
                    float inter = __fmul_rn(iw, ih);
                    float denom = __fadd_rn(__fadd_rn(__fadd_rn(ia, ja), -inter), 1e-9f);
                    sup = __fdiv_rn(inter, denom) > NMS_T;
                }
                unsigned bits = __ballot_sync(0xffffffffu, sup);
                if (l == 0) maskw[i*10 + w] = bits;
            }
        }
    }
    __syncthreads();

    // ---- sequential greedy scan (warp 0; lane k holds keep word k) ----
    if (tid < 32) {
        unsigned kw = (tid < 10) ? validw[tid] : 0u;
        for (int i = 0; i < MD; ++i) {
            unsigned m   = (tid < 10) ? maskw[i*10 + tid] : 0u;  // prefetch
            unsigned wrd = __shfl_sync(0xffffffffu, kw, i >> 5);
            if ((wrd >> (i & 31)) & 1u) kw &= ~m;
        }
        if (tid < 10) keepw[tid] = kw;
    }
    __syncthreads();

    if (tid < MD) {
        unsigned kp = (keepw[tid >> 5] >> (tid & 31)) & 1u;
        size_t o = (size_t)b * MD + tid;
        out[OF_KEEP + o] = (float)kp;
        out[OF_INZ  + o] = (kp && inside[tid]) ? 1.f : 0.f;
    }
}

extern "C" void kernel_launch(void* const* d_in, const int* in_sizes, int n_in,
                              void* d_out, int out_size)
{
    const float* pred = (const float*)d_in[0];
    const float* zone = (const float*)d_in[1];
    float* out = (float*)d_out;
    score_kernel<<<TOTAL / 128, 128>>>(pred);
    nms_kernel<<<NB, 512>>>(zone, out);
}

// round 2
// speedup vs baseline: 1.9386x; 1.9386x over previous
#include <cuda_runtime.h>

#define NB   32
#define NA   8400
#define ROWF 85
#define MD   300
#define TOTAL (NB*NA)
#define CONF_T 0.2f
#define NMS_T  0.45f
#define NTH  640

// output layout: concatenated float32, reference return order
#define OF_BOX  0         // 32*300*4 = 38400
#define OF_INZ  38400     // 9600
#define OF_SC   48000     // 9600
#define OF_CLS  57600     // 9600
#define OF_CTR  67200     // 19200
#define OF_KEEP 86400     // 9600  -> total 96000

__device__ unsigned long long g_keys[TOTAL];   // (ordered score)<<32 | ~anchor_idx
__device__ float4 g_aux[TOTAL*2];              // [x1,y1,x2,y2] , [obj,conf,cls,0]

// ---------------------------------------------------------------------------
// Kernel A: per-anchor score/decode. Memory bound (91.4 MB read).
// ---------------------------------------------------------------------------
__global__ void __launch_bounds__(128) score_kernel(const float* __restrict__ pred)
{
    __shared__ float sm[128 * ROWF];
    const float4* src = reinterpret_cast<const float4*>(pred) +
                        (size_t)blockIdx.x * (128 * ROWF / 4);
    float4* dst = reinterpret_cast<float4*>(sm);
#pragma unroll
    for (int i = threadIdx.x; i < 128 * ROWF / 4; i += 128) dst[i] = src[i];
    __syncthreads();

    const int t = threadIdx.x;
    const float* a = sm + t * ROWF;                 // stride 85: conflict-free

    float x = a[0], y = a[1], w = a[2], h = a[3], obj = a[4];

    float m0 = a[5], m1 = a[6], m2 = a[7], m3 = a[8];
#pragma unroll
    for (int k = 9; k < 85; k += 4) {
        m0 = fmaxf(m0, a[k]);   m1 = fmaxf(m1, a[k+1]);
        m2 = fmaxf(m2, a[k+2]); m3 = fmaxf(m3, a[k+3]);
    }
    float conf = fmaxf(fmaxf(m0, m1), fmaxf(m2, m3));

    int cls = 0;
#pragma unroll
    for (int k = 79; k >= 0; --k) { if (a[5+k] == conf) cls = k; }

    float score = __fmul_rn(obj, conf);             // bit-exact vs reference

    int g    = blockIdx.x * 128 + t;
    int aidx = g % NA;

    unsigned long long key = 0ull;
    if (score >= CONF_T) {
        unsigned ub = __float_as_uint(score) | 0x80000000u;  // score>0: ordered
        key = ((unsigned long long)ub << 32) | (unsigned)(~(unsigned)aidx);
    }
    g_keys[g] = key;

    float hw = __fmul_rn(w, 0.5f), hh = __fmul_rn(h, 0.5f);
    g_aux[2*g]   = make_float4(__fadd_rn(x,-hw), __fadd_rn(y,-hh),
                               __fadd_rn(x, hw), __fadd_rn(y, hh));
    g_aux[2*g+1] = make_float4(obj, conf, (float)cls, 0.f);
}

// ---------------------------------------------------------------------------
// Kernel B: per-batch block (640 thr). 2x12-bit radix-select (warp-aggregated
// hist + parallel suffix-scan threshold) -> bitonic 512 -> mask (tile-skipped)
// -> sequential scan -> outputs.
// ---------------------------------------------------------------------------
__global__ void __launch_bounds__(NTH) nms_kernel(const float* __restrict__ zone,
                                                  float* __restrict__ out)
{
    __shared__ unsigned hist[4096];
    __shared__ unsigned suf[512];
    __shared__ unsigned sh_bin, sh_acc, ncand;
    __shared__ unsigned long long cand[512];
    __shared__ float4 bbox[MD];
    __shared__ float  bA[MD];
    __shared__ int    inside[MD];
    __shared__ unsigned maskw[MD * 10];
    __shared__ unsigned keepw[10];
    __shared__ unsigned validw[10];

    const int b   = blockIdx.x;
    const int tid = threadIdx.x;
    const unsigned long long* __restrict__ keys = g_keys + (size_t)b * NA;

    if (tid == 0) { sh_bin = 0u; sh_acc = 0u; ncand = 0u; }
    if (tid < 10) validw[tid] = 0u;

    unsigned thresh24 = 0u;

    // ---- two 12-bit radix passes over the top 24 bits of the ordered score ----
#pragma unroll
    for (int pass = 0; pass < 2; ++pass) {
        for (int i = tid; i < 4096; i += NTH) hist[i] = 0u;
        __syncthreads();

        unsigned p0 = sh_bin;          // pass-0 winner (ignored on pass 0)
        unsigned need = (unsigned)MD - sh_acc;

        for (int i = tid; i < NA; i += NTH) {
            unsigned long long k = keys[i];
            unsigned d;
            bool take;
            if (pass == 0) { d = (unsigned)(k >> 52); take = true; }
            else { d = (unsigned)(k >> 40) & 0xFFFu;
                   take = ((unsigned)(k >> 52) == p0); }
            if (take) {
                unsigned am = __activemask();
                unsigned mm = __match_any_sync(am, d);
                if ((tid & 31) == (int)(__ffs(mm) - 1u))
                    atomicAdd(&hist[d], (unsigned)__popc(mm));
            }
        }
        __syncthreads();

        // group sums: 512 groups of 8 bins
        if (tid < 512) {
            unsigned s = 0;
#pragma unroll
            for (int k = 0; k < 8; ++k) s += hist[tid * 8 + k];
            suf[tid] = s;
        }
        __syncthreads();
        // inclusive suffix scan: suf[t] = sum over groups t..511
#pragma unroll
        for (int st = 1; st < 512; st <<= 1) {
            unsigned v = 0;
            if (tid < 512 && tid + st < 512) v = suf[tid + st];
            __syncthreads();
            if (tid < 512) suf[tid] += v;
            __syncthreads();
        }
        // locate threshold group, then bin within group (8 serial steps)
        if (tid < 512) {
            unsigned here  = suf[tid];
            unsigned above = (tid == 511) ? 0u : suf[tid + 1];
            if (here >= need && above < need) {
                unsigned cum = above; int sel = 0;
#pragma unroll
                for (int k = 7; k >= 0; --k) {
                    unsigned c = hist[tid * 8 + k];
                    if (cum + c >= need) { sel = k; break; }
                    cum += c;
                }
                sh_bin = (unsigned)(tid * 8 + sel);
                sh_acc += cum;              // count strictly above selected bin
            }
        }
        __syncthreads();
        if (pass == 1) thresh24 = (p0 << 12) | sh_bin;
    }

    // ---- collect candidates with 24-bit prefix >= threshold (<= ~512) ----
    for (int i = tid; i < NA; i += NTH) {
        unsigned long long k = keys[i];
        if ((unsigned)(k >> 40) >= thresh24) {
            unsigned p = atomicAdd(&ncand, 1u);
            if (p < 512u) cand[p] = k;
        }
    }
    __syncthreads();
    {
        unsigned nc = ncand; if (nc > 512u) nc = 512u;
        if (tid < 512 && (unsigned)tid >= nc) cand[tid] = 0ull;
    }

    // ---- bitonic sort 512 desc (exact top_k order incl. tie-break) ----
    for (int size = 2; size <= 512; size <<= 1) {
        for (int stride = size >> 1; stride > 0; stride >>= 1) {
            __syncthreads();
            if (tid < 512) {
                int partner = tid ^ stride;
                if (partner > tid) {
                    unsigned long long u = cand[tid], v = cand[partner];
                    bool desc = ((tid & size) == 0);
                    if (desc ? (u < v) : (u > v)) { cand[tid] = v; cand[partner] = u; }
                }
            }
        }
    }
    __syncthreads();

    // ---- gather top 300, order-independent outputs, zone test ----
    if (tid < MD) {
        unsigned long long kk = cand[tid];
        unsigned aidx = ~((unsigned)kk);
        bool valid = (kk >> 32) != 0ull;
        if (!valid) aidx = 0;
        size_t g = (size_t)b * NA + aidx;
        float4 v0 = g_aux[2*g], v1 = g_aux[2*g+1];
        bbox[tid] = v0;
        bA[tid] = __fmul_rn(fmaxf(__fadd_rn(v0.z, -v0.x), 0.f),
                            fmaxf(__fadd_rn(v0.w, -v0.y), 0.f));
        if (valid) atomicOr(&validw[tid >> 5], 1u << (tid & 31));

        float cx = __fmul_rn(__fadd_rn(v0.x, v0.z), 0.5f);
        float cy = __fmul_rn(__fadd_rn(v0.y, v0.w), 0.5f);

        int cnt = 0;
#pragma unroll
        for (int k2 = 0; k2 < 8; ++k2) {
            int km = (k2 + 7) & 7;
            float xi = zone[2*k2], yi = zone[2*k2+1];
            float xj = zone[2*km], yj = zone[2*km+1];
            bool gyi = yi > cy, gyj = yj > cy;
            if (gyi != gyj) {
                float gx = __fadd_rn(
                    __fdiv_rn(__fmul_rn(__fadd_rn(xj,-xi), __fadd_rn(cy,-yi)),
                              __fadd_rn(yj,-yi)), xi);
                if (gx > cx) cnt++;
            }
        }
        inside[tid] = cnt & 1;

        size_t o = (size_t)b * MD + tid;
        out[OF_BOX + o*4 + 0] = v0.y;  out[OF_BOX + o*4 + 1] = v0.x;
        out[OF_BOX + o*4 + 2] = v0.w;  out[OF_BOX + o*4 + 3] = v0.z;
        out[OF_SC  + o]       = fmaxf(v1.x, v1.y);
        out[OF_CLS + o]       = v1.z;
        out[OF_CTR + o*2]     = cy;    out[OF_CTR + o*2 + 1] = cx;
    }
    __syncthreads();

    // ---- suppression bitmask: 20 warps = 10 column chunks x 2 row halves ----
    {
        int w = tid >> 5, l = tid & 31;
        int c  = w % 10;                       // column chunk
        int r0 = (w < 10) ? 0 : 150;
        int r1 = r0 + 150;
        int j  = c * 32 + l;
        int jmax = c * 32 + 31;
        bool jv = (j < MD);
        float4 bj = jv ? bbox[j] : make_float4(0,0,0,0);
        float  ja = jv ? bA[j] : 0.f;
        for (int i = r0; i < r1; ++i) {
            unsigned bits = 0u;
            if (jmax > i) {                    // uniform per warp; else all j<=i
                float4 bi = bbox[i];
                float  ia = bA[i];
                bool sup = false;
                if (jv && j > i) {
                    float ltx = fmaxf(bi.x, bj.x), lty = fmaxf(bi.y, bj.y);
                    float rbx = fminf(bi.z, bj.z), rby = fminf(bi.w, bj.w);
                    float iw  = fmaxf(__fadd_rn(rbx, -ltx), 0.f);
                    float ih  = fmaxf(__fadd_rn(rby, -lty), 0.f);
                    float inter = __fmul_rn(iw, ih);
                    float denom = __fadd_rn(__fadd_rn(__fadd_rn(ia, ja), -inter), 1e-9f);
                    sup = inter > __fmul_rn(NMS_T, denom);   // == inter/denom > T
                }
                bits = __ballot_sync(0xffffffffu, sup);
            }
            if (l == 0) maskw[i*10 + c] = bits;
        }
    }
    __syncthreads();

    // ---- sequential greedy scan (warp 0; lane k holds keep word k) ----
    if (tid < 32) {
        unsigned kw = (tid < 10) ? validw[tid] : 0u;
        for (int i = 0; i < MD; ++i) {
            unsigned m   = (tid < 10) ? maskw[i*10 + tid] : 0u;  // prefetch
            unsigned wrd = __shfl_sync(0xffffffffu, kw, i >> 5);
            if ((wrd >> (i & 31)) & 1u) kw &= ~m;
        }
        if (tid < 10) keepw[tid] = kw;
    }
    __syncthreads();

    if (tid < MD) {
        unsigned kp = (keepw[tid >> 5] >> (tid & 31)) & 1u;
        size_t o = (size_t)b * MD + tid;
        out[OF_KEEP + o] = (float)kp;
        out[OF_INZ  + o] = (kp && inside[tid]) ? 1.f : 0.f;
    }
}

extern "C" void kernel_launch(void* const* d_in, const int* in_sizes, int n_in,
                              void* d_out, int out_size)
{
    const float* pred = (const float*)d_in[0];
    const float* zone = (const float*)d_in[1];
    float* out = (float*)d_out;
    score_kernel<<<TOTAL / 128, 128>>>(pred);
    nms_kernel<<<NB, NTH>>>(zone, out);
}

// round 3
// speedup vs baseline: 2.1575x; 1.1129x over previous
#include <cuda_runtime.h>

#define NB   32
#define NA   8400
#define ROWF 85
#define MD   300
#define TOTAL (NB*NA)
#define CONF_T 0.2f
#define NMS_T  0.45f

// output layout: concatenated float32, reference return order
#define OF_BOX  0         // 32*300*4 = 38400
#define OF_INZ  38400     // 9600
#define OF_SC   48000     // 9600
#define OF_CLS  57600     // 9600
#define OF_CTR  67200     // 19200
#define OF_KEEP 86400     // 9600  -> total 96000

__device__ unsigned long long g_keys[TOTAL];   // (ordered score)<<32 | ~anchor_idx
__device__ float4   g_aux[TOTAL*2];            // [x1,y1,x2,y2],[obj,conf,cls,0]
__device__ float4   g_sbox[NB*MD];             // sorted boxes
__device__ float    g_sarea[NB*MD];
__device__ unsigned g_flags[NB*20];            // [0..9] valid words, [10..19] inside words
__device__ unsigned g_mask[NB*MD*10];          // suppression bitmask

// ---------------------------------------------------------------------------
// Kernel A: per-anchor score/decode. Memory bound (91.4 MB read).
// ---------------------------------------------------------------------------
__global__ void __launch_bounds__(128) score_kernel(const float* __restrict__ pred)
{
    __shared__ float sm[128 * ROWF];
    const float4* src = reinterpret_cast<const float4*>(pred) +
                        (size_t)blockIdx.x * (128 * ROWF / 4);
    float4* dst = reinterpret_cast<float4*>(sm);
#pragma unroll
    for (int i = threadIdx.x; i < 128 * ROWF / 4; i += 128) dst[i] = src[i];
    __syncthreads();

    const int t = threadIdx.x;
    const float* a = sm + t * ROWF;

    float x = a[0], y = a[1], w = a[2], h = a[3], obj = a[4];

    float m0 = a[5], m1 = a[6], m2 = a[7], m3 = a[8];
#pragma unroll
    for (int k = 9; k < 85; k += 4) {
        m0 = fmaxf(m0, a[k]);   m1 = fmaxf(m1, a[k+1]);
        m2 = fmaxf(m2, a[k+2]); m3 = fmaxf(m3, a[k+3]);
    }
    float conf = fmaxf(fmaxf(m0, m1), fmaxf(m2, m3));

    int cls = 0;
#pragma unroll
    for (int k = 79; k >= 0; --k) { if (a[5+k] == conf) cls = k; }

    float score = __fmul_rn(obj, conf);

    int g    = blockIdx.x * 128 + t;
    int aidx = g % NA;

    unsigned long long key = 0ull;
    if (score >= CONF_T) {
        unsigned ub = __float_as_uint(score) | 0x80000000u;
        key = ((unsigned long long)ub << 32) | (unsigned)(~(unsigned)aidx);
    }
    g_keys[g] = key;

    float hw = __fmul_rn(w, 0.5f), hh = __fmul_rn(h, 0.5f);
    g_aux[2*g]   = make_float4(__fadd_rn(x,-hw), __fadd_rn(y,-hh),
                               __fadd_rn(x, hw), __fadd_rn(y, hh));
    g_aux[2*g+1] = make_float4(obj, conf, (float)cls, 0.f);
}

// ---------------------------------------------------------------------------
// Kernel B: per-batch select+sort. Keys staged in smem; 2x12-bit radix select
// with 3-barrier hierarchical threshold scan; bitonic 512; gather + outputs.
// ---------------------------------------------------------------------------
struct SelSmem {
    unsigned shi[NA];
    unsigned slo[NA];
    unsigned hist[4096];
    unsigned s8[512];
    unsigned sgsuf[33];
    unsigned long long cand[512];
    unsigned sh_bin, sh_acc, ncand;
    unsigned validw[10], inw[10];
};
#define SEL_SMEM_BYTES (sizeof(SelSmem))

__global__ void __launch_bounds__(1024) select_kernel(const float* __restrict__ zone,
                                                      float* __restrict__ out)
{
    extern __shared__ char smem_raw[];
    SelSmem& S = *reinterpret_cast<SelSmem*>(smem_raw);

    const int b   = blockIdx.x;
    const int tid = threadIdx.x;

    // ---- stage keys: split hi/lo for conflict-free 4B-stride access ----
    {
        const unsigned long long* __restrict__ keys = g_keys + (size_t)b * NA;
        for (int i = tid; i < NA; i += 1024) {
            unsigned long long k = keys[i];
            S.shi[i] = (unsigned)(k >> 32);
            S.slo[i] = (unsigned)k;
        }
    }
    if (tid == 0) { S.sh_bin = 0u; S.sh_acc = 0u; S.ncand = 0u; }
    if (tid < 10) { S.validw[tid] = 0u; S.inw[tid] = 0u; }

    unsigned thresh24 = 0u;

#pragma unroll
    for (int pass = 0; pass < 2; ++pass) {
        for (int i = tid; i < 4096; i += 1024) S.hist[i] = 0u;
        __syncthreads();

        unsigned p0   = S.sh_bin;
        unsigned need = (unsigned)MD - S.sh_acc;

        for (int i = tid; i < NA; i += 1024) {
            unsigned hi = S.shi[i];
            unsigned d;
            bool take;
            if (pass == 0) { d = hi >> 20; take = true; }
            else           { d = (hi >> 8) & 0xFFFu; take = ((hi >> 20) == p0); }
            if (take) {
                unsigned am = __activemask();
                unsigned mm = __match_any_sync(am, d);
                if ((tid & 31) == (int)(__ffs(mm) - 1u))
                    atomicAdd(&S.hist[d], (unsigned)__popc(mm));
            }
        }
        __syncthreads();

        // group sums of 8 bins
        if (tid < 512) {
            unsigned s = 0;
#pragma unroll
            for (int k = 0; k < 8; ++k) s += S.hist[tid * 8 + k];
            S.s8[tid] = s;
        }
        __syncthreads();
        // warp 0: supergroup (128-bin) sums + shfl suffix scan
        if (tid < 32) {
            unsigned s = 0;
#pragma unroll
            for (int k = 0; k < 16; ++k) s += S.s8[tid * 16 + k];
#pragma unroll
            for (int off = 1; off < 32; off <<= 1) {
                unsigned v = __shfl_down_sync(0xffffffffu, s, off);
                if (tid + off < 32) s += v;
            }
            S.sgsuf[tid] = s;                  // inclusive suffix over supergroups
            if (tid == 0) S.sgsuf[32] = 0u;
        }
        __syncthreads();
        if (tid < 512) {
            int g = tid >> 4;
            unsigned ws = 0;
            for (int j = tid + 1; j < (g + 1) * 16; ++j) ws += S.s8[j];
            unsigned above = S.sgsuf[g + 1] + ws;     // count in groups strictly above tid
            unsigned here  = above + S.s8[tid];
            if (here >= need && above < need) {
                unsigned cum = above; int sel = 0;
#pragma unroll
                for (int k = 7; k >= 0; --k) {
                    unsigned c = S.hist[tid * 8 + k];
                    if (cum + c >= need) { sel = k; break; }
                    cum += c;
                }
                S.sh_bin = (unsigned)(tid * 8 + sel);
                S.sh_acc += cum;
            }
        }
        __syncthreads();
        if (pass == 1) thresh24 = (p0 << 12) | S.sh_bin;
    }

    // ---- collect candidates with 24-bit prefix >= threshold ----
    for (int i = tid; i < NA; i += 1024) {
        unsigned hi = S.shi[i];
        if ((hi >> 8) >= thresh24) {
            unsigned p = atomicAdd(&S.ncand, 1u);
            if (p < 512u)
                S.cand[p] = ((unsigned long long)hi << 32) | S.slo[i];
        }
    }
    __syncthreads();
    {
        unsigned nc = S.ncand; if (nc > 512u) nc = 512u;
        if (tid < 512 && (unsigned)tid >= nc) S.cand[tid] = 0ull;
    }

    // ---- bitonic sort 512 desc ----
    for (int size = 2; size <= 512; size <<= 1) {
        for (int stride = size >> 1; stride > 0; stride >>= 1) {
            __syncthreads();
            if (tid < 512) {
                int partner = tid ^ stride;
                if (partner > tid) {
                    unsigned long long u = S.cand[tid], v = S.cand[partner];
                    bool desc = ((tid & size) == 0);
                    if (desc ? (u < v) : (u > v)) { S.cand[tid] = v; S.cand[partner] = u; }
                }
            }
        }
    }
    __syncthreads();

    // ---- gather top 300, order-independent outputs, zone test ----
    if (tid < MD) {
        unsigned long long kk = S.cand[tid];
        unsigned aidx = ~((unsigned)kk);
        bool valid = (kk >> 32) != 0ull;
        if (!valid) aidx = 0;
        size_t g = (size_t)b * NA + aidx;
        float4 v0 = g_aux[2*g], v1 = g_aux[2*g+1];

        float area = __fmul_rn(fmaxf(__fadd_rn(v0.z, -v0.x), 0.f),
                               fmaxf(__fadd_rn(v0.w, -v0.y), 0.f));
        g_sbox[b*MD + tid]  = v0;
        g_sarea[b*MD + tid] = area;
        if (valid) atomicOr(&S.validw[tid >> 5], 1u << (tid & 31));

        float cx = __fmul_rn(__fadd_rn(v0.x, v0.z), 0.5f);
        float cy = __fmul_rn(__fadd_rn(v0.y, v0.w), 0.5f);

        int cnt = 0;
#pragma unroll
        for (int k2 = 0; k2 < 8; ++k2) {
            int km = (k2 + 7) & 7;
            float xi = zone[2*k2], yi = zone[2*k2+1];
            float xj = zone[2*km], yj = zone[2*km+1];
            bool gyi = yi > cy, gyj = yj > cy;
            if (gyi != gyj) {
                float gx = __fadd_rn(
                    __fdiv_rn(__fmul_rn(__fadd_rn(xj,-xi), __fadd_rn(cy,-yi)),
                              __fadd_rn(yj,-yi)), xi);
                if (gx > cx) cnt++;
            }
        }
        if (cnt & 1) atomicOr(&S.inw[tid >> 5], 1u << (tid & 31));

        size_t o = (size_t)b * MD + tid;
        out[OF_BOX + o*4 + 0] = v0.y;  out[OF_BOX + o*4 + 1] = v0.x;
        out[OF_BOX + o*4 + 2] = v0.w;  out[OF_BOX + o*4 + 3] = v0.z;
        out[OF_SC  + o]       = fmaxf(v1.x, v1.y);
        out[OF_CLS + o]       = v1.z;
        out[OF_CTR + o*2]     = cy;    out[OF_CTR + o*2 + 1] = cx;
    }
    __syncthreads();
    if (tid < 10) {
        g_flags[b*20 + tid]      = S.validw[tid];
        g_flags[b*20 + 10 + tid] = S.inw[tid];
    }
}

// ---------------------------------------------------------------------------
// Kernel C: suppression bitmask on the full chip. 320 blocks (32 batches x 10
// row groups of 30), 640 threads = 10 column chunks x 2 row halves.
// ---------------------------------------------------------------------------
__global__ void __launch_bounds__(640) mask_kernel()
{
    __shared__ float4 sbb[MD];
    __shared__ float  sA[MD];

    const int b  = blockIdx.x / 10;
    const int rg = blockIdx.x % 10;
    const int tid = threadIdx.x;

    if (tid < MD) { sbb[tid] = g_sbox[b*MD + tid]; sA[tid] = g_sarea[b*MD + tid]; }
    __syncthreads();

    int w = tid >> 5, l = tid & 31;
    int c    = w % 10;
    int half = w / 10;
    int i0   = rg * 30 + half * 15;
    int j    = c * 32 + l;
    int jmax = c * 32 + 31;
    bool jv  = (j < MD);
    float4 bj = jv ? sbb[j] : make_float4(0,0,0,0);
    float  ja = jv ? sA[j] : 0.f;

    for (int i = i0; i < i0 + 15; ++i) {
        unsigned bits = 0u;
        if (jmax > i) {
            float4 bi = sbb[i];
            float  ia = sA[i];
            bool sup = false;
            if (jv && j > i) {
                float ltx = fmaxf(bi.x, bj.x), lty = fmaxf(bi.y, bj.y);
                float rbx = fminf(bi.z, bj.z), rby = fminf(bi.w, bj.w);
                float iw  = fmaxf(__fadd_rn(rbx, -ltx), 0.f);
                float ih  = fmaxf(__fadd_rn(rby, -lty), 0.f);
                float inter = __fmul_rn(iw, ih);
                float denom = __fadd_rn(__fadd_rn(__fadd_rn(ia, ja), -inter), 1e-9f);
                sup = inter > __fmul_rn(NMS_T, denom);
            }
            bits = __ballot_sync(0xffffffffu, sup);
        }
        if (l == 0) g_mask[(b*MD + i)*10 + c] = bits;
    }
}

// ---------------------------------------------------------------------------
// Kernel D: sequential greedy scan per batch + keep/inzone outputs.
// ---------------------------------------------------------------------------
__global__ void __launch_bounds__(512) fin_kernel(float* __restrict__ out)
{
    __shared__ unsigned smask[MD*10];
    __shared__ unsigned keepw[10];
    __shared__ unsigned flg[20];

    const int b   = blockIdx.x;
    const int tid = threadIdx.x;

    for (int i = tid; i < MD*10; i += 512) smask[i] = g_mask[b*MD*10 + i];
    if (tid < 20) flg[tid] = g_flags[b*20 + tid];
    __syncthreads();

    if (tid < 32) {
        unsigned kw = (tid < 10) ? flg[tid] : 0u;
        for (int i = 0; i < MD; ++i) {
            unsigned m   = (tid < 10) ? smask[i*10 + tid] : 0u;
            unsigned wrd = __shfl_sync(0xffffffffu, kw, i >> 5);
            if ((wrd >> (i & 31)) & 1u) kw &= ~m;
        }
        if (tid < 10) keepw[tid] = kw;
    }
    __syncthreads();

    if (tid < MD) {
        unsigned kp = (keepw[tid >> 5] >> (tid & 31)) & 1u;
        unsigned in = (flg[10 + (tid >> 5)] >> (tid & 31)) & 1u;
        size_t o = (size_t)b * MD + tid;
        out[OF_KEEP + o] = (float)kp;
        out[OF_INZ  + o] = (kp && in) ? 1.f : 0.f;
    }
}

extern "C" void kernel_launch(void* const* d_in, const int* in_sizes, int n_in,
                              void* d_out, int out_size)
{
    const float* pred = (const float*)d_in[0];
    const float* zone = (const float*)d_in[1];
    float* out = (float*)d_out;

    static int attr_done = 0;
    if (!attr_done) {
        cudaFuncSetAttribute(select_kernel,
                             cudaFuncAttributeMaxDynamicSharedMemorySize,
                             (int)SEL_SMEM_BYTES);
        attr_done = 1;
    }

    score_kernel<<<TOTAL / 128, 128>>>(pred);
    select_kernel<<<NB, 1024, SEL_SMEM_BYTES>>>(zone, out);
    mask_kernel<<<NB * 10, 640>>>();
    fin_kernel<<<NB, 512>>>(out);
}

// round 4
// speedup vs baseline: 2.2647x; 1.0497x over previous
#include <cuda_runtime.h>

#define NB   32
#define NA   8400
#define ROWF 85
#define MD   300
#define TOTAL (NB*NA)
#define CONF_T 0.2f
#define NMS_T  0.45f

// output layout: concatenated float32, reference return order
#define OF_BOX  0         // 32*300*4 = 38400
#define OF_INZ  38400     // 9600
#define OF_SC   48000     // 9600
#define OF_CLS  57600     // 9600
#define OF_CTR  67200     // 19200
#define OF_KEEP 86400     // 9600  -> total 96000

__device__ unsigned long long g_keys[TOTAL];   // (ordered score)<<32 | ~anchor_idx
__device__ float4   g_sbox[NB*MD];             // sorted boxes
__device__ float    g_sarea[NB*MD];
__device__ unsigned g_flags[NB*20];            // [0..9] valid, [10..19] inside
__device__ unsigned g_mask[NB*MD*10];          // suppression bitmask

// ---------------------------------------------------------------------------
// Kernel A: per-anchor score only (keys). Memory bound: 91.4 MB read, 2.1 MB write.
// ---------------------------------------------------------------------------
__global__ void __launch_bounds__(128) score_kernel(const float* __restrict__ pred)
{
    __shared__ float sm[128 * ROWF];
    const float4* src = reinterpret_cast<const float4*>(pred) +
                        (size_t)blockIdx.x * (128 * ROWF / 4);
    float4* dst = reinterpret_cast<float4*>(sm);
#pragma unroll
    for (int i = threadIdx.x; i < 128 * ROWF / 4; i += 128) dst[i] = src[i];
    __syncthreads();

    const int t = threadIdx.x;
    const float* a = sm + t * ROWF;

    float obj = a[4];
    float m0 = a[5], m1 = a[6], m2 = a[7], m3 = a[8];
#pragma unroll
    for (int k = 9; k < 85; k += 4) {
        m0 = fmaxf(m0, a[k]);   m1 = fmaxf(m1, a[k+1]);
        m2 = fmaxf(m2, a[k+2]); m3 = fmaxf(m3, a[k+3]);
    }
    float conf  = fmaxf(fmaxf(m0, m1), fmaxf(m2, m3));
    float score = __fmul_rn(obj, conf);

    int g    = blockIdx.x * 128 + t;
    int aidx = g % NA;

    unsigned long long key = 0ull;
    if (score >= CONF_T) {
        unsigned ub = __float_as_uint(score) | 0x80000000u;
        key = ((unsigned long long)ub << 32) | (unsigned)(~(unsigned)aidx);
    }
    g_keys[g] = key;
}

// ---------------------------------------------------------------------------
// Kernel B: per-batch select+sort. Keys in smem; 2x12-bit radix select;
// hybrid shfl/smem bitonic 512; re-decode winners from pred; outputs.
// ---------------------------------------------------------------------------
struct SelSmem {
    unsigned shi[NA];
    unsigned slo[NA];
    unsigned hist[4096];
    unsigned s8[512];
    unsigned sgsuf[33];
    unsigned long long cand[512];
    unsigned sh_bin, sh_acc, ncand;
    unsigned validw[10], inw[10];
};
#define SEL_SMEM_BYTES (sizeof(SelSmem))

__global__ void __launch_bounds__(1024) select_kernel(const float* __restrict__ pred,
                                                      const float* __restrict__ zone,
                                                      float* __restrict__ out)
{
    extern __shared__ char smem_raw[];
    SelSmem& S = *reinterpret_cast<SelSmem*>(smem_raw);

    const int b   = blockIdx.x;
    const int tid = threadIdx.x;

    {
        const unsigned long long* __restrict__ keys = g_keys + (size_t)b * NA;
        for (int i = tid; i < NA; i += 1024) {
            unsigned long long k = keys[i];
            S.shi[i] = (unsigned)(k >> 32);
            S.slo[i] = (unsigned)k;
        }
    }
    if (tid == 0) { S.sh_bin = 0u; S.sh_acc = 0u; S.ncand = 0u; }
    if (tid < 10) { S.validw[tid] = 0u; S.inw[tid] = 0u; }

    unsigned thresh24 = 0u;

#pragma unroll
    for (int pass = 0; pass < 2; ++pass) {
        for (int i = tid; i < 4096; i += 1024) S.hist[i] = 0u;
        __syncthreads();

        unsigned p0   = S.sh_bin;
        unsigned need = (unsigned)MD - S.sh_acc;

        for (int i = tid; i < NA; i += 1024) {
            unsigned hi = S.shi[i];
            unsigned d;
            bool take;
            if (pass == 0) { d = hi >> 20; take = true; }
            else           { d = (hi >> 8) & 0xFFFu; take = ((hi >> 20) == p0); }
            if (take) {
                unsigned am = __activemask();
                unsigned mm = __match_any_sync(am, d);
                if ((tid & 31) == (int)(__ffs(mm) - 1u))
                    atomicAdd(&S.hist[d], (unsigned)__popc(mm));
            }
        }
        __syncthreads();

        if (tid < 512) {
            unsigned s = 0;
#pragma unroll
            for (int k = 0; k < 8; ++k) s += S.hist[tid * 8 + k];
            S.s8[tid] = s;
        }
        __syncthreads();
        if (tid < 32) {
            unsigned s = 0;
#pragma unroll
            for (int k = 0; k < 16; ++k) s += S.s8[tid * 16 + k];
#pragma unroll
            for (int off = 1; off < 32; off <<= 1) {
                unsigned v = __shfl_down_sync(0xffffffffu, s, off);
                if (tid + off < 32) s += v;
            }
            S.sgsuf[tid] = s;
            if (tid == 0) S.sgsuf[32] = 0u;
        }
        __syncthreads();
        if (tid < 512) {
            int g = tid >> 4;
            unsigned ws = 0;
            for (int j = tid + 1; j < (g + 1) * 16; ++j) ws += S.s8[j];
            unsigned above = S.sgsuf[g + 1] + ws;
            unsigned here  = above + S.s8[tid];
            if (here >= need && above < need) {
                unsigned cum = above; int sel = 0;
#pragma unroll
                for (int k = 7; k >= 0; --k) {
                    unsigned c = S.hist[tid * 8 + k];
                    if (cum + c >= need) { sel = k; break; }
                    cum += c;
                }
                S.sh_bin = (unsigned)(tid * 8 + sel);
                S.sh_acc += cum;
            }
        }
        __syncthreads();
        if (pass == 1) thresh24 = (p0 << 12) | S.sh_bin;
    }

    // ---- collect candidates ----
    for (int i = tid; i < NA; i += 1024) {
        unsigned hi = S.shi[i];
        if ((hi >> 8) >= thresh24) {
            unsigned p = atomicAdd(&S.ncand, 1u);
            if (p < 512u)
                S.cand[p] = ((unsigned long long)hi << 32) | S.slo[i];
        }
    }
    __syncthreads();
    {
        unsigned nc = S.ncand; if (nc > 512u) nc = 512u;
        if (tid < 512 && (unsigned)tid >= nc) S.cand[tid] = 0ull;
    }
    __syncthreads();

    // ---- bitonic sort 512 desc: register element, shfl for stride<32 ----
    unsigned long long v = (tid < 512) ? S.cand[tid] : 0ull;
    for (int size = 2; size <= 512; size <<= 1) {
        for (int stride = size >> 1; stride > 0; stride >>= 1) {
            if (stride >= 32) {
                __syncthreads();
                if (tid < 512) S.cand[tid] = v;
                __syncthreads();
                if (tid < 512) {
                    unsigned long long vp = S.cand[tid ^ stride];
                    bool takeMax = ((tid & stride) == 0) == ((tid & size) == 0);
                    v = takeMax ? (v > vp ? v : vp) : (v < vp ? v : vp);
                }
            } else if (tid < 512) {
                unsigned long long vp = __shfl_xor_sync(0xffffffffu, v, stride);
                bool takeMax = ((tid & stride) == 0) == ((tid & size) == 0);
                v = takeMax ? (v > vp ? v : vp) : (v < vp ? v : vp);
            }
        }
    }

    // ---- re-decode winners from pred; outputs; zone test ----
    if (tid < MD) {
        unsigned long long kk = v;
        unsigned aidx = ~((unsigned)kk);
        bool valid = (kk >> 32) != 0ull;
        if (!valid) aidx = 0;
        const float* a = pred + (size_t)(b * NA + aidx) * ROWF;

        float x = a[0], y = a[1], w = a[2], h = a[3], obj = a[4];

        float conf = a[5]; int cls = 0;
#pragma unroll 8
        for (int k = 1; k < 80; ++k) {
            float c = a[5 + k];
            if (c > conf) { conf = c; cls = k; }       // first-max == jnp.argmax
        }

        float hw = __fmul_rn(w, 0.5f), hh = __fmul_rn(h, 0.5f);
        float4 v0 = make_float4(__fadd_rn(x,-hw), __fadd_rn(y,-hh),
                                __fadd_rn(x, hw), __fadd_rn(y, hh));

        float area = __fmul_rn(fmaxf(__fadd_rn(v0.z, -v0.x), 0.f),
                               fmaxf(__fadd_rn(v0.w, -v0.y), 0.f));
        g_sbox[b*MD + tid]  = v0;
        g_sarea[b*MD + tid] = area;
        if (valid) atomicOr(&S.validw[tid >> 5], 1u << (tid & 31));

        float cx = __fmul_rn(__fadd_rn(v0.x, v0.z), 0.5f);
        float cy = __fmul_rn(__fadd_rn(v0.y, v0.w), 0.5f);

        int cnt = 0;
#pragma unroll
        for (int k2 = 0; k2 < 8; ++k2) {
            int km = (k2 + 7) & 7;
            float xi = zone[2*k2], yi = zone[2*k2+1];
            float xj = zone[2*km], yj = zone[2*km+1];
            bool gyi = yi > cy, gyj = yj > cy;
            if (gyi != gyj) {
                float gx = __fadd_rn(
                    __fdiv_rn(__fmul_rn(__fadd_rn(xj,-xi), __fadd_rn(cy,-yi)),
                              __fadd_rn(yj,-yi)), xi);
                if (gx > cx) cnt++;
            }
        }
        if (cnt & 1) atomicOr(&S.inw[tid >> 5], 1u << (tid & 31));

        size_t o = (size_t)b * MD + tid;
        out[OF_BOX + o*4 + 0] = v0.y;  out[OF_BOX + o*4 + 1] = v0.x;
        out[OF_BOX + o*4 + 2] = v0.w;  out[OF_BOX + o*4 + 3] = v0.z;
        out[OF_SC  + o]       = fmaxf(obj, conf);
        out[OF_CLS + o]       = (float)cls;
        out[OF_CTR + o*2]     = cy;    out[OF_CTR + o*2 + 1] = cx;
    }
    __syncthreads();
    if (tid < 10) {
        g_flags[b*20 + tid]      = S.validw[tid];
        g_flags[b*20 + 10 + tid] = S.inw[tid];
    }
}

// ---------------------------------------------------------------------------
// Kernel C: suppression bitmask on the full chip (320 blocks).
// ---------------------------------------------------------------------------
__global__ void __launch_bounds__(640) mask_kernel()
{
    __shared__ float4 sbb[MD];
    __shared__ float  sA[MD];

    const int b  = blockIdx.x / 10;
    const int rg = blockIdx.x % 10;
    const int tid = threadIdx.x;

    if (tid < MD) { sbb[tid] = g_sbox[b*MD + tid]; sA[tid] = g_sarea[b*MD + tid]; }
    __syncthreads();

    int w = tid >> 5, l = tid & 31;
    int c    = w % 10;
    int half = w / 10;
    int i0   = rg * 30 + half * 15;
    int j    = c * 32 + l;
    int jmax = c * 32 + 31;
    bool jv  = (j < MD);
    float4 bj = jv ? sbb[j] : make_float4(0,0,0,0);
    float  ja = jv ? sA[j] : 0.f;

    for (int i = i0; i < i0 + 15; ++i) {
        unsigned bits = 0u;
        if (jmax > i) {
            float4 bi = sbb[i];
            float  ia = sA[i];
            bool sup = false;
            if (jv && j > i) {
                float ltx = fmaxf(bi.x, bj.x), lty = fmaxf(bi.y, bj.y);
                float rbx = fminf(bi.z, bj.z), rby = fminf(bi.w, bj.w);
                float iw  = fmaxf(__fadd_rn(rbx, -ltx), 0.f);
                float ih  = fmaxf(__fadd_rn(rby, -lty), 0.f);
                float inter = __fmul_rn(iw, ih);
                float denom = __fadd_rn(__fadd_rn(__fadd_rn(ia, ja), -inter), 1e-9f);
                sup = inter > __fmul_rn(NMS_T, denom);
            }
            bits = __ballot_sync(0xffffffffu, sup);
        }
        if (l == 0) g_mask[(b*MD + i)*10 + c] = bits;
    }
}

// ---------------------------------------------------------------------------
// Kernel D: block-closure greedy scan (no shfl/LDS in the serial chain).
// ---------------------------------------------------------------------------
__global__ void __launch_bounds__(512) fin_kernel(float* __restrict__ out)
{
    __shared__ unsigned smask[320*10];          // rows 300..319 zeroed
    __shared__ unsigned keepw[10];
    __shared__ unsigned flg[20];

    const int b   = blockIdx.x;
    const int tid = threadIdx.x;

    for (int i = tid; i < MD*10; i += 512) smask[i] = g_mask[b*MD*10 + i];
    for (int i = MD*10 + tid; i < 320*10; i += 512) smask[i] = 0u;
    if (tid < 20) flg[tid] = g_flags[b*20 + tid];
    __syncthreads();

    if (tid < 32) {
        const int l = tid;
        unsigned kw = (l < 10) ? flg[l] : 0u;

        for (int blk = 0; blk < 10; ++blk) {
            unsigned alive = __shfl_sync(0xffffffffu, kw, blk);
            const unsigned base = (unsigned)blk * 32u;

            // every lane loads the 32 diagonal words (LDS broadcast, independent)
            unsigned r[32];
#pragma unroll
            for (int k = 0; k < 32; ++k)
                r[k] = smask[(base + k)*10 + blk];

            // register-only sequential closure over 32 rows
#pragma unroll
            for (int k = 0; k < 32; ++k)
                alive &= ~(r[k] & (0u - ((alive >> k) & 1u)));

            // apply kept rows' masks to all keep words (idempotent on word blk)
            if (l < 10) {
#pragma unroll 4
                for (int k = 0; k < 32; ++k)
                    if ((alive >> k) & 1u)
                        kw &= ~smask[(base + k)*10 + l];
            }
        }
        if (l < 10) keepw[l] = kw;
    }
    __syncthreads();

    if (tid < MD) {
        unsigned kp = (keepw[tid >> 5] >> (tid & 31)) & 1u;
        unsigned in = (flg[10 + (tid >> 5)] >> (tid & 31)) & 1u;
        size_t o = (size_t)b * MD + tid;
        out[OF_KEEP + o] = (float)kp;
        out[OF_INZ  + o] = (kp && in) ? 1.f : 0.f;
    }
}

extern "C" void kernel_launch(void* const* d_in, const int* in_sizes, int n_in,
                              void* d_out, int out_size)
{
    const float* pred = (const float*)d_in[0];
    const float* zone = (const float*)d_in[1];
    float* out = (float*)d_out;

    static int attr_done = 0;
    if (!attr_done) {
        cudaFuncSetAttribute(select_kernel,
                             cudaFuncAttributeMaxDynamicSharedMemorySize,
                             (int)SEL_SMEM_BYTES);
        attr_done = 1;
    }

    score_kernel<<<TOTAL / 128, 128>>>(pred);
    select_kernel<<<NB, 1024, SEL_SMEM_BYTES>>>(pred, zone, out);
    mask_kernel<<<NB * 10, 640>>>();
    fin_kernel<<<NB, 512>>>(out);
}